// round 3
// baseline (speedup 1.0000x reference)
#include <cuda_runtime.h>
#include <math.h>

#define NMAX 4096
#define NPIX (96*96)
#define NTILE 144
#define NWORDS (NMAX/32)

// ---- packed scratch (device globals) ----
__device__ float4 g_p0[NMAX];   // u0, u1, rc2, hA
__device__ float4 g_p1[NMAX];   // hB, hC, alpha, cr
__device__ float2 g_p2[NMAX];   // cg, cb
__device__ unsigned long long g_key[NMAX];
// depth-sorted
__device__ float4 o_p0[NMAX];
__device__ float4 o_p1[NMAX];
__device__ float2 o_p2[NMAX];
// per-tile survivor bitmasks (bit index == sorted rank)
__device__ unsigned g_mask[NTILE * NWORDS];

// ---------------- Kernel A: per-gaussian preprocess ----------------
__global__ void prep_kernel(const float* __restrict__ pws,
                            const float* __restrict__ lows,
                            const float* __restrict__ highs,
                            const float* __restrict__ araw,
                            const float* __restrict__ sraw,
                            const float* __restrict__ qraw,
                            const float* __restrict__ Rcw,
                            const float* __restrict__ tcw,
                            const float* __restrict__ cam,
                            float* __restrict__ out_areas,
                            int n)
{
    int i = blockIdx.x * blockDim.x + threadIdx.x;
    if (i >= n) return;

    float fx = cam[0], fy = cam[1], cx = cam[2], cy = cam[3];
    float R00=Rcw[0],R01=Rcw[1],R02=Rcw[2];
    float R10=Rcw[3],R11=Rcw[4],R12=Rcw[5];
    float R20=Rcw[6],R21=Rcw[7],R22=Rcw[8];
    float t0=tcw[0],t1=tcw[1],t2=tcw[2];

    float pwx=pws[3*i], pwy=pws[3*i+1], pwz=pws[3*i+2];
    float pcx = R00*pwx + R01*pwy + R02*pwz + t0;
    float pcy = R10*pwx + R11*pwy + R12*pwz + t1;
    float pcz = R20*pwx + R21*pwy + R22*pwz + t2;
    float depth = pcz;
    float zs = (depth > 1e-6f) ? depth : 1e-6f;
    float inv_z = 1.0f / zs;
    float u0 = fx * pcx * inv_z + cx;
    float u1 = fy * pcy * inv_z + cy;

    float s0 = expf(sraw[3*i]), s1 = expf(sraw[3*i+1]), s2 = expf(sraw[3*i+2]);
    float qw=qraw[4*i], qx=qraw[4*i+1], qy=qraw[4*i+2], qz=qraw[4*i+3];
    float qn = rsqrtf(qw*qw + qx*qx + qy*qy + qz*qz);
    qw*=qn; qx*=qn; qy*=qn; qz*=qn;
    float r00 = 1.f-2.f*(qy*qy+qz*qz), r01 = 2.f*(qx*qy-qw*qz), r02 = 2.f*(qx*qz+qw*qy);
    float r10 = 2.f*(qx*qy+qw*qz), r11 = 1.f-2.f*(qx*qx+qz*qz), r12 = 2.f*(qy*qz-qw*qx);
    float r20 = 2.f*(qx*qz-qw*qy), r21 = 2.f*(qy*qz+qw*qx), r22 = 1.f-2.f*(qx*qx+qy*qy);

    float v0=s0*s0, v1=s1*s1, v2=s2*s2;
    float c00 = v0*r00*r00 + v1*r01*r01 + v2*r02*r02;
    float c01 = v0*r00*r10 + v1*r01*r11 + v2*r02*r12;
    float c02 = v0*r00*r20 + v1*r01*r21 + v2*r02*r22;
    float c11 = v0*r10*r10 + v1*r11*r11 + v2*r12*r12;
    float c12 = v0*r10*r20 + v1*r11*r21 + v2*r12*r22;
    float c22 = v0*r20*r20 + v1*r21*r21 + v2*r22*r22;

    float limx = 1.3f * (96.0f / (2.0f*fx));
    float limy = 1.3f * (96.0f / (2.0f*fy));
    float txc = fminf(fmaxf(pcx*inv_z, -limx), limx) * zs;
    float tyc = fminf(fmaxf(pcy*inv_z, -limy), limy) * zs;
    float J00 = fx*inv_z, J02 = -fx*txc*inv_z*inv_z;
    float J11 = fy*inv_z, J12 = -fy*tyc*inv_z*inv_z;

    float T00 = J00*R00 + J02*R20, T01 = J00*R01 + J02*R21, T02 = J00*R02 + J02*R22;
    float T10 = J11*R10 + J12*R20, T11 = J11*R11 + J12*R21, T12 = J11*R12 + J12*R22;

    float m00 = T00*c00 + T01*c01 + T02*c02;
    float m01 = T00*c01 + T01*c11 + T02*c12;
    float m02 = T00*c02 + T01*c12 + T02*c22;
    float m10 = T10*c00 + T11*c01 + T12*c02;
    float m11 = T10*c01 + T11*c11 + T12*c12;
    float m12 = T10*c02 + T11*c12 + T12*c22;

    float A  = m00*T00 + m01*T01 + m02*T02 + 0.3f;
    float Bb = m00*T10 + m01*T11 + m02*T12;
    float Cc = m10*T10 + m11*T11 + m12*T12 + 0.3f;

    float det  = A*Cc - Bb*Bb;
    float idet = 1.0f / det;
    float hA = -0.5f * Cc * idet;
    float hC = -0.5f * A  * idet;
    float hB =  Bb * idet;

    float mid = 0.5f * (A + Cc);
    float lam = mid + sqrtf(fmaxf(mid*mid - det, 0.1f));
    float radius = ceilf(3.0f * sqrtf(lam));
    out_areas[2*i]   = radius;
    out_areas[2*i+1] = radius;

    float alpha = 1.0f / (1.0f + expf(-araw[i]));
    if (!(depth > 0.2f)) alpha = 0.0f;

    float rc2;
    if (alpha * 255.0f <= 1.0f) {
        rc2 = -1.0f;
    } else {
        float theta = 2.0f * logf(255.0f * alpha);
        rc2 = lam * theta * 1.002f + 1e-2f;
    }

    // SH color
    float wx = R00*t0 + R10*t1 + R20*t2;
    float wy = R01*t0 + R11*t1 + R21*t2;
    float wz = R02*t0 + R12*t1 + R22*t2;
    float dx0 = pwx + wx, dy0 = pwy + wy, dz0 = pwz + wz;
    float dn = rsqrtf(dx0*dx0 + dy0*dy0 + dz0*dz0);
    float x = dx0*dn, y = dy0*dn, z = dz0*dn;
    float xx=x*x, yy=y*y, zz=z*z, xy=x*y, yz=y*z, xz=x*z;

    float b1 = -0.4886025119029199f*y, b2 = 0.4886025119029199f*z, b3 = -0.4886025119029199f*x;
    float b4 =  1.0925484305920792f  * xy;
    float b5 = -1.0925484305920792f  * yz;
    float b6 =  0.31539156525252005f * (2.f*zz - xx - yy);
    float b7 = -1.0925484305920792f  * xz;
    float b8 =  0.5462742152960396f  * (xx - yy);
    float b9  = -0.5900435899266435f * y * (3.f*xx - yy);
    float b10 =  2.890611442640554f  * xy * z;
    float b11 = -0.4570457994644658f * y * (4.f*zz - xx - yy);
    float b12 =  0.3731763325901154f * z * (2.f*zz - 3.f*xx - 3.f*yy);
    float b13 = -0.4570457994644658f * x * (4.f*zz - xx - yy);
    float b14 =  1.445305721320277f  * z * (xx - yy);
    float b15 = -0.5900435899266435f * x * (xx - 3.f*yy);

    const float* hs = highs + 45*i;
    float col[3];
    #pragma unroll
    for (int ch = 0; ch < 3; ch++) {
        float c = 0.28209479177387814f * lows[3*i + ch];
        c += b1  * hs[0*3+ch]  + b2  * hs[1*3+ch]  + b3  * hs[2*3+ch];
        c += b4  * hs[3*3+ch]  + b5  * hs[4*3+ch]  + b6  * hs[5*3+ch];
        c += b7  * hs[6*3+ch]  + b8  * hs[7*3+ch];
        c += b9  * hs[8*3+ch]  + b10 * hs[9*3+ch]  + b11 * hs[10*3+ch];
        c += b12 * hs[11*3+ch] + b13 * hs[12*3+ch] + b14 * hs[13*3+ch];
        c += b15 * hs[14*3+ch];
        col[ch] = fmaxf(c + 0.5f, 0.0f);
    }

    g_p0[i] = make_float4(u0, u1, rc2, hA);
    g_p1[i] = make_float4(hB, hC, alpha, col[0]);
    g_p2[i] = make_float2(col[1], col[2]);

    unsigned int b = __float_as_uint(depth);
    b = (b & 0x80000000u) ? ~b : (b | 0x80000000u);
    g_key[i] = ((unsigned long long)b << 32) | (unsigned int)i;
}

// ---------------- Kernel B: rank-by-counting (exact stable argsort + gather) ----------------
__global__ void rank_kernel(int n)
{
    __shared__ unsigned long long sk[NMAX];
    int tid = threadIdx.x;
    for (int k = tid; k < n; k += 256) sk[k] = g_key[k];
    __syncthreads();

    int il = tid >> 3;
    int sp = tid & 7;
    int i  = blockIdx.x * 32 + il;
    if (i >= n) return;
    unsigned long long ki = sk[i];

    int r = 0;
    #pragma unroll 8
    for (int j = sp; j < n; j += 8) r += (sk[j] < ki) ? 1 : 0;

    r += __shfl_down_sync(0xffffffffu, r, 4, 8);
    r += __shfl_down_sync(0xffffffffu, r, 2, 8);
    r += __shfl_down_sync(0xffffffffu, r, 1, 8);

    if (sp == 0) {
        o_p0[r] = g_p0[i];
        o_p1[r] = g_p1[i];
        o_p2[r] = g_p2[i];
    }
}

// ---------------- Kernel C: per-tile cull -> bitmask over sorted ranks ----------------
__global__ void cull_kernel(int n)
{
    int tile = blockIdx.x;
    float x0 = (float)((tile % 12) * 8), x1 = x0 + 7.0f;
    float y0 = (float)((tile / 12) * 8), y1 = y0 + 7.0f;
    int tid = threadIdx.x, warp = tid >> 5, lane = tid & 31;

    int kmax = (n + 255) >> 8;
    for (int k = 0; k < kmax; k++) {
        int gi = k * 256 + tid;
        bool keep = false;
        if (gi < n) {
            float4 p0 = o_p0[gi];
            float ddx = fmaxf(fmaxf(x0 - p0.x, p0.x - x1), 0.0f);
            float ddy = fmaxf(fmaxf(y0 - p0.y, p0.y - y1), 0.0f);
            keep = (ddx*ddx + ddy*ddy) <= p0.z;
        }
        unsigned m = __ballot_sync(0xffffffffu, keep);
        if (lane == 0) g_mask[tile * NWORDS + k * 8 + warp] = m;
    }
}

// ---------------- Kernel D: blend (mask expand + staged composite) ----------------
#define BT 128
__global__ void blend_kernel(float* __restrict__ out, int n)
{
    __shared__ unsigned swords[NWORDS];
    __shared__ int wsum[4];
    __shared__ unsigned short slist[NMAX];
    __shared__ float4 sp0[BT];
    __shared__ float4 sp1[BT];
    __shared__ float2 sp2[BT];

    int tile = blockIdx.x;
    int tid = threadIdx.x;
    int lane = tid & 31, warp = tid >> 5;
    int nwords = (n + 31) >> 5;

    if (tid < nwords) swords[tid] = g_mask[tile * NWORDS + tid];
    __syncthreads();

    int c = (tid < nwords) ? __popc(swords[tid]) : 0;
    int v = c;
    #pragma unroll
    for (int o = 1; o < 32; o <<= 1) {
        int u = __shfl_up_sync(0xffffffffu, v, o);
        if (lane >= o) v += u;
    }
    if (lane == 31) wsum[warp] = v;
    __syncthreads();
    int add = 0;
    #pragma unroll
    for (int w = 0; w < 4; w++) if (w < warp) add += wsum[w];
    int excl = v - c + add;
    int cnt = wsum[0] + wsum[1] + wsum[2] + wsum[3];

    if (tid < nwords && c) {
        unsigned m = swords[tid];
        int slot = excl, base = tid * 32;
        while (m) {
            int b = __ffs(m) - 1; m &= m - 1;
            slist[slot++] = (unsigned short)(base + b);
        }
    }
    __syncthreads();

    int px = tid & 7, py = (tid >> 3) & 7;
    float fpx = (float)((tile % 12) * 8 + px);
    float fpy = (float)((tile / 12) * 8 + py);
    float tau = (tid < 64) ? 1.0f : 0.0f;
    float a0 = 0.f, a1 = 0.f, a2 = 0.f;

    for (int seg = 0; seg < cnt; seg += BT) {
        int t = seg + tid;
        if (t < cnt) {
            int gi = slist[t];
            sp0[tid] = o_p0[gi];
            sp1[tid] = o_p1[gi];
            sp2[tid] = o_p2[gi];
        }
        __syncthreads();
        int mseg = min(BT, cnt - seg);
        if (tau > 1e-4f) {
            for (int s = 0; s < mseg; s++) {
                float4 q0 = sp0[s];
                float4 q1 = sp1[s];
                float ddx = q0.x - fpx, ddy = q0.y - fpy;
                float p = q0.w*ddx*ddx + q1.y*ddy*ddy + q1.x*ddx*ddy;
                p = fminf(p, 0.0f);
                float ap = fminf(q1.z * __expf(p), 0.99f);
                if (ap >= (1.0f/255.0f)) {
                    float wgt = ap * tau;
                    float2 q2 = sp2[s];
                    a0 += q1.w * wgt;
                    a1 += q2.x * wgt;
                    a2 += q2.y * wgt;
                    tau *= (1.0f - ap);
                    if (tau <= 1e-4f) break;
                }
            }
        }
        if (__syncthreads_and(tau <= 1e-4f)) break;
    }

    if (tid < 64) {
        int pix = ((tile / 12) * 8 + py) * 96 + (tile % 12) * 8 + px;
        out[pix]          = a0;
        out[NPIX + pix]   = a1;
        out[2*NPIX + pix] = a2;
    }
}

extern "C" void kernel_launch(void* const* d_in, const int* in_sizes, int n_in,
                              void* d_out, int out_size)
{
    const float* pws   = (const float*)d_in[0];
    const float* lows  = (const float*)d_in[1];
    const float* highs = (const float*)d_in[2];
    const float* araw  = (const float*)d_in[3];
    const float* sraw  = (const float*)d_in[4];
    const float* qraw  = (const float*)d_in[5];
    const float* Rcw   = (const float*)d_in[7];
    const float* tcw   = (const float*)d_in[8];
    const float* cam   = (const float*)d_in[9];
    float* out = (float*)d_out;

    int n = in_sizes[0] / 3;
    if (n > NMAX) n = NMAX;

    float* out_areas = out + 3 * NPIX;

    prep_kernel<<<(n + 63) / 64, 64>>>(pws, lows, highs, araw, sraw, qraw,
                                       Rcw, tcw, cam, out_areas, n);
    rank_kernel<<<(n + 31) / 32, 256>>>(n);
    cull_kernel<<<NTILE, 256>>>(n);
    blend_kernel<<<NTILE, BT>>>(out, n);
}

// round 6
// speedup vs baseline: 3.9895x; 3.9895x over previous
#include <cuda_runtime.h>
#include <math.h>

#define NMAX 4096
#define NPIX (96*96)
#define NTILE 144
#define NWORDS (NMAX/32)

// ---- packed scratch (device globals) ----
__device__ float4 g_p0[NMAX];   // u0, u1, rc2, hA
__device__ float4 g_p1[NMAX];   // hB, hC, alpha, cr
__device__ float2 g_p2[NMAX];   // cg, cb
__device__ unsigned long long g_key[NMAX];
// depth-sorted
__device__ float4 o_p0[NMAX];
__device__ float4 o_p1[NMAX];
__device__ float2 o_p2[NMAX];

// ---------------- Kernel A: per-gaussian preprocess ----------------
__global__ void __launch_bounds__(64, 1)
prep_kernel(const float* __restrict__ pws,
            const float* __restrict__ lows,
            const float* __restrict__ highs,
            const float* __restrict__ araw,
            const float* __restrict__ sraw,
            const float* __restrict__ qraw,
            const float* __restrict__ Rcw,
            const float* __restrict__ tcw,
            const float* __restrict__ cam,
            float* __restrict__ out_areas,
            int n)
{
    int i = blockIdx.x * blockDim.x + threadIdx.x;
    if (i >= n) return;

    float fx = cam[0], fy = cam[1], cx = cam[2], cy = cam[3];
    float R00=Rcw[0],R01=Rcw[1],R02=Rcw[2];
    float R10=Rcw[3],R11=Rcw[4],R12=Rcw[5];
    float R20=Rcw[6],R21=Rcw[7],R22=Rcw[8];
    float t0=tcw[0],t1=tcw[1],t2=tcw[2];

    float pwx=pws[3*i], pwy=pws[3*i+1], pwz=pws[3*i+2];
    float pcx = R00*pwx + R01*pwy + R02*pwz + t0;
    float pcy = R10*pwx + R11*pwy + R12*pwz + t1;
    float pcz = R20*pwx + R21*pwy + R22*pwz + t2;
    float depth = pcz;
    float zs = (depth > 1e-6f) ? depth : 1e-6f;
    float inv_z = 1.0f / zs;
    float u0 = fx * pcx * inv_z + cx;
    float u1 = fy * pcy * inv_z + cy;

    float s0 = expf(sraw[3*i]), s1 = expf(sraw[3*i+1]), s2 = expf(sraw[3*i+2]);
    float qw=qraw[4*i], qx=qraw[4*i+1], qy=qraw[4*i+2], qz=qraw[4*i+3];
    float qn = rsqrtf(qw*qw + qx*qx + qy*qy + qz*qz);
    qw*=qn; qx*=qn; qy*=qn; qz*=qn;
    float r00 = 1.f-2.f*(qy*qy+qz*qz), r01 = 2.f*(qx*qy-qw*qz), r02 = 2.f*(qx*qz+qw*qy);
    float r10 = 2.f*(qx*qy+qw*qz), r11 = 1.f-2.f*(qx*qx+qz*qz), r12 = 2.f*(qy*qz-qw*qx);
    float r20 = 2.f*(qx*qz-qw*qy), r21 = 2.f*(qy*qz+qw*qx), r22 = 1.f-2.f*(qx*qx+qy*qy);

    float v0=s0*s0, v1=s1*s1, v2=s2*s2;
    float c00 = v0*r00*r00 + v1*r01*r01 + v2*r02*r02;
    float c01 = v0*r00*r10 + v1*r01*r11 + v2*r02*r12;
    float c02 = v0*r00*r20 + v1*r01*r21 + v2*r02*r22;
    float c11 = v0*r10*r10 + v1*r11*r11 + v2*r12*r12;
    float c12 = v0*r10*r20 + v1*r11*r21 + v2*r12*r22;
    float c22 = v0*r20*r20 + v1*r21*r21 + v2*r22*r22;

    float limx = 1.3f * (96.0f / (2.0f*fx));
    float limy = 1.3f * (96.0f / (2.0f*fy));
    float txc = fminf(fmaxf(pcx*inv_z, -limx), limx) * zs;
    float tyc = fminf(fmaxf(pcy*inv_z, -limy), limy) * zs;
    float J00 = fx*inv_z, J02 = -fx*txc*inv_z*inv_z;
    float J11 = fy*inv_z, J12 = -fy*tyc*inv_z*inv_z;

    float T00 = J00*R00 + J02*R20, T01 = J00*R01 + J02*R21, T02 = J00*R02 + J02*R22;
    float T10 = J11*R10 + J12*R20, T11 = J11*R11 + J12*R21, T12 = J11*R12 + J12*R22;

    float m00 = T00*c00 + T01*c01 + T02*c02;
    float m01 = T00*c01 + T01*c11 + T02*c12;
    float m02 = T00*c02 + T01*c12 + T02*c22;
    float m10 = T10*c00 + T11*c01 + T12*c02;
    float m11 = T10*c01 + T11*c11 + T12*c12;
    float m12 = T10*c02 + T11*c12 + T12*c22;

    float A  = m00*T00 + m01*T01 + m02*T02 + 0.3f;
    float Bb = m00*T10 + m01*T11 + m02*T12;
    float Cc = m10*T10 + m11*T11 + m12*T12 + 0.3f;

    float det  = A*Cc - Bb*Bb;
    float idet = 1.0f / det;
    float hA = -0.5f * Cc * idet;
    float hC = -0.5f * A  * idet;
    float hB =  Bb * idet;

    float mid = 0.5f * (A + Cc);
    float lam = mid + sqrtf(fmaxf(mid*mid - det, 0.1f));
    float radius = ceilf(3.0f * sqrtf(lam));
    out_areas[2*i]   = radius;
    out_areas[2*i+1] = radius;

    float alpha = 1.0f / (1.0f + __expf(-araw[i]));
    if (!(depth > 0.2f)) alpha = 0.0f;

    float rc2;
    if (alpha * 255.0f <= 1.0f) {
        rc2 = -1.0f;
    } else {
        float theta = 2.0f * __logf(255.0f * alpha);
        rc2 = lam * theta * 1.002f + 1e-2f;
    }

    // SH color
    float wx = R00*t0 + R10*t1 + R20*t2;
    float wy = R01*t0 + R11*t1 + R21*t2;
    float wz = R02*t0 + R12*t1 + R22*t2;
    float dx0 = pwx + wx, dy0 = pwy + wy, dz0 = pwz + wz;
    float dn = rsqrtf(dx0*dx0 + dy0*dy0 + dz0*dz0);
    float x = dx0*dn, y = dy0*dn, z = dz0*dn;
    float xx=x*x, yy=y*y, zz=z*z, xy=x*y, yz=y*z, xz=x*z;

    float b1 = -0.4886025119029199f*y, b2 = 0.4886025119029199f*z, b3 = -0.4886025119029199f*x;
    float b4 =  1.0925484305920792f  * xy;
    float b5 = -1.0925484305920792f  * yz;
    float b6 =  0.31539156525252005f * (2.f*zz - xx - yy);
    float b7 = -1.0925484305920792f  * xz;
    float b8 =  0.5462742152960396f  * (xx - yy);
    float b9  = -0.5900435899266435f * y * (3.f*xx - yy);
    float b10 =  2.890611442640554f  * xy * z;
    float b11 = -0.4570457994644658f * y * (4.f*zz - xx - yy);
    float b12 =  0.3731763325901154f * z * (2.f*zz - 3.f*xx - 3.f*yy);
    float b13 = -0.4570457994644658f * x * (4.f*zz - xx - yy);
    float b14 =  1.445305721320277f  * z * (xx - yy);
    float b15 = -0.5900435899266435f * x * (xx - 3.f*yy);

    const float* hs = highs + 45*i;
    float col[3];
    #pragma unroll
    for (int ch = 0; ch < 3; ch++) {
        float c = 0.28209479177387814f * lows[3*i + ch];
        c += b1  * hs[0*3+ch]  + b2  * hs[1*3+ch]  + b3  * hs[2*3+ch];
        c += b4  * hs[3*3+ch]  + b5  * hs[4*3+ch]  + b6  * hs[5*3+ch];
        c += b7  * hs[6*3+ch]  + b8  * hs[7*3+ch];
        c += b9  * hs[8*3+ch]  + b10 * hs[9*3+ch]  + b11 * hs[10*3+ch];
        c += b12 * hs[11*3+ch] + b13 * hs[12*3+ch] + b14 * hs[13*3+ch];
        c += b15 * hs[14*3+ch];
        col[ch] = fmaxf(c + 0.5f, 0.0f);
    }

    g_p0[i] = make_float4(u0, u1, rc2, hA);
    g_p1[i] = make_float4(hB, hC, alpha, col[0]);
    g_p2[i] = make_float2(col[1], col[2]);

    unsigned int b = __float_as_uint(depth);
    b = (b & 0x80000000u) ? ~b : (b | 0x80000000u);
    g_key[i] = ((unsigned long long)b << 32) | (unsigned int)i;
}

// ---------------- Kernel B: rank-by-counting (exact stable argsort + gather) ----------------
__global__ void rank_kernel(int n)
{
    __shared__ unsigned long long sk[NMAX];
    int tid = threadIdx.x;
    for (int k = tid; k < n; k += 256) sk[k] = g_key[k];
    __syncthreads();

    int il = tid >> 3;
    int sp = tid & 7;
    int i  = blockIdx.x * 32 + il;
    if (i >= n) return;
    unsigned long long ki = sk[i];

    int r = 0;
    #pragma unroll 8
    for (int j = sp; j < n; j += 8) r += (sk[j] < ki) ? 1 : 0;

    r += __shfl_down_sync(0xffffffffu, r, 4, 8);
    r += __shfl_down_sync(0xffffffffu, r, 2, 8);
    r += __shfl_down_sync(0xffffffffu, r, 1, 8);

    if (sp == 0) {
        o_p0[r] = g_p0[i];
        o_p1[r] = g_p1[i];
        o_p2[r] = g_p2[i];
    }
}

// ---------------- Kernel C: fused cull + segmented-parallel blend ----------------
// 144 tiles x 256 threads. 8 warps each composite a depth-segment of survivors
// for all 64 pixels (2 px/thread), partials folded per pixel at the end.
__global__ void blend_kernel(float* __restrict__ out, int n)
{
    __shared__ unsigned swords[NWORDS];
    __shared__ int wsum[4];
    __shared__ unsigned short slist[NMAX];
    __shared__ float4 st0[8][32];
    __shared__ float4 st1[8][32];
    __shared__ float2 st2[8][32];
    __shared__ float4 part[8][64];

    int tile = blockIdx.x;
    int tid = threadIdx.x, lane = tid & 31, warp = tid >> 5;
    float x0 = (float)((tile % 12) * 8), x1 = x0 + 7.0f;
    float y0 = (float)((tile / 12) * 8), y1 = y0 + 7.0f;

    // ---- phase A: cull -> bitmasks in smem ----
    int nwords = (n + 31) >> 5;
    int kmax = (n + 255) >> 8;
    for (int k = 0; k < kmax; k++) {
        int gi = k * 256 + tid;
        bool keep = false;
        if (gi < n) {
            float4 p0 = o_p0[gi];
            float ddx = fmaxf(fmaxf(x0 - p0.x, p0.x - x1), 0.0f);
            float ddy = fmaxf(fmaxf(y0 - p0.y, p0.y - y1), 0.0f);
            keep = (ddx*ddx + ddy*ddy) <= p0.z;
        }
        unsigned m = __ballot_sync(0xffffffffu, keep);
        if (lane == 0) swords[k * 8 + warp] = m;
    }
    __syncthreads();

    // ---- phase B: scan + expand to ordered survivor list ----
    int c = 0, v = 0;
    if (tid < 128) {
        c = (tid < nwords) ? __popc(swords[tid]) : 0;
        v = c;
        #pragma unroll
        for (int o = 1; o < 32; o <<= 1) {
            int u = __shfl_up_sync(0xffffffffu, v, o);
            if (lane >= o) v += u;
        }
        if (lane == 31) wsum[warp] = v;
    }
    __syncthreads();
    int cnt = wsum[0] + wsum[1] + wsum[2] + wsum[3];
    if (tid < nwords && c) {
        int add = 0;
        #pragma unroll
        for (int w = 0; w < 4; w++) if (w < warp) add += wsum[w];
        int slot = v - c + add;
        unsigned m = swords[tid];
        int base = tid * 32;
        while (m) {
            int b = __ffs(m) - 1; m &= m - 1;
            slist[slot++] = (unsigned short)(base + b);
        }
    }
    __syncthreads();

    // ---- phase C: per-warp segment composite ----
    int Lw = (cnt + 7) >> 3;
    int seg0 = warp * Lw;
    int seg1 = min(seg0 + Lw, cnt);

    int px = lane & 7, py = lane >> 3;
    float fpx  = x0 + (float)px;
    float fpy0 = y0 + (float)py;
    float fpy1 = fpy0 + 4.0f;

    float tau0 = 1.f, tau1 = 1.f;
    float A00=0.f, A01=0.f, A02=0.f, A10=0.f, A11=0.f, A12=0.f;

    for (int cs = seg0; cs < seg1; cs += 32) {
        int t = cs + lane;
        if (t < seg1) {
            int gi = slist[t];
            st0[warp][lane] = o_p0[gi];
            st1[warp][lane] = o_p1[gi];
            st2[warp][lane] = o_p2[gi];
        }
        __syncwarp();
        int m = min(32, seg1 - cs);
        for (int s = 0; s < m; s++) {
            float4 q0 = st0[warp][s];
            float4 q1 = st1[warp][s];
            float2 q2 = st2[warp][s];
            float ddx  = q0.x - fpx;
            float bx   = q1.x * ddx;            // hB*dx
            float base = q0.w * ddx * ddx;      // hA*dx^2
            float ddy0 = q0.y - fpy0;
            float ddy1 = q0.y - fpy1;
            float p0 = base + q1.y*ddy0*ddy0 + bx*ddy0;
            float p1 = base + q1.y*ddy1*ddy1 + bx*ddy1;
            float ap0 = fminf(q1.z * __expf(fminf(p0, 0.f)), 0.99f);
            float ap1 = fminf(q1.z * __expf(fminf(p1, 0.f)), 0.99f);
            if (ap0 < (1.0f/255.0f)) ap0 = 0.f;
            if (ap1 < (1.0f/255.0f)) ap1 = 0.f;
            float w0 = ap0 * tau0, w1 = ap1 * tau1;
            A00 += q1.w * w0; A01 += q2.x * w0; A02 += q2.y * w0;
            A10 += q1.w * w1; A11 += q2.x * w1; A12 += q2.y * w1;
            tau0 -= tau0 * ap0;
            tau1 -= tau1 * ap1;
        }
        __syncwarp();
    }
    part[warp][lane]      = make_float4(A00, A01, A02, tau0);
    part[warp][lane + 32] = make_float4(A10, A11, A12, tau1);
    __syncthreads();

    // ---- phase D: fold partials per pixel ----
    if (tid < 64) {
        float T = 1.f, a0 = 0.f, a1 = 0.f, a2 = 0.f;
        #pragma unroll
        for (int w = 0; w < 8; w++) {
            float4 q = part[w][tid];
            if (T > 1e-4f) {
                a0 += T * q.x; a1 += T * q.y; a2 += T * q.z;
                T *= q.w;
            }
        }
        int ppx = tid & 7, ppy = tid >> 3;
        int pix = ((tile / 12) * 8 + ppy) * 96 + (tile % 12) * 8 + ppx;
        out[pix]          = a0;
        out[NPIX + pix]   = a1;
        out[2*NPIX + pix] = a2;
    }
}

extern "C" void kernel_launch(void* const* d_in, const int* in_sizes, int n_in,
                              void* d_out, int out_size)
{
    const float* pws   = (const float*)d_in[0];
    const float* lows  = (const float*)d_in[1];
    const float* highs = (const float*)d_in[2];
    const float* araw  = (const float*)d_in[3];
    const float* sraw  = (const float*)d_in[4];
    const float* qraw  = (const float*)d_in[5];
    const float* Rcw   = (const float*)d_in[7];
    const float* tcw   = (const float*)d_in[8];
    const float* cam   = (const float*)d_in[9];
    float* out = (float*)d_out;

    int n = in_sizes[0] / 3;
    if (n > NMAX) n = NMAX;

    float* out_areas = out + 3 * NPIX;

    prep_kernel<<<(n + 63) / 64, 64>>>(pws, lows, highs, araw, sraw, qraw,
                                       Rcw, tcw, cam, out_areas, n);
    rank_kernel<<<(n + 31) / 32, 256>>>(n);
    blend_kernel<<<NTILE, 256>>>(out, n);
}

// round 8
// speedup vs baseline: 4.1455x; 1.0391x over previous
#include <cuda_runtime.h>
#include <math.h>

#define NMAX 4096
#define NPIX (96*96)
#define NTILE 144
#define NWORDS (NMAX/32)
#define NSEG 16

// ---- packed scratch (device globals) ----
__device__ float4 g_p0[NMAX];   // u0, u1, rc2, hA
__device__ float4 g_p1[NMAX];   // hB, hC, alpha, cr
__device__ float2 g_p2[NMAX];   // cg, cb
__device__ unsigned long long g_key[NMAX];
// depth-sorted
__device__ float4 o_p0[NMAX];
__device__ float4 o_p1[NMAX];
__device__ float2 o_p2[NMAX];

// ---------------- Kernel A: per-gaussian preprocess ----------------
__global__ void __launch_bounds__(32, 1)
prep_kernel(const float* __restrict__ pws,
            const float* __restrict__ lows,
            const float* __restrict__ highs,
            const float* __restrict__ araw,
            const float* __restrict__ sraw,
            const float* __restrict__ qraw,
            const float* __restrict__ Rcw,
            const float* __restrict__ tcw,
            const float* __restrict__ cam,
            float* __restrict__ out_areas,
            int n)
{
    int i = blockIdx.x * blockDim.x + threadIdx.x;
    if (i >= n) return;

    float fx = cam[0], fy = cam[1], cx = cam[2], cy = cam[3];
    float R00=Rcw[0],R01=Rcw[1],R02=Rcw[2];
    float R10=Rcw[3],R11=Rcw[4],R12=Rcw[5];
    float R20=Rcw[6],R21=Rcw[7],R22=Rcw[8];
    float t0=tcw[0],t1=tcw[1],t2=tcw[2];

    float pwx=pws[3*i], pwy=pws[3*i+1], pwz=pws[3*i+2];
    float pcx = R00*pwx + R01*pwy + R02*pwz + t0;
    float pcy = R10*pwx + R11*pwy + R12*pwz + t1;
    float pcz = R20*pwx + R21*pwy + R22*pwz + t2;
    float depth = pcz;
    float zs = (depth > 1e-6f) ? depth : 1e-6f;
    float inv_z = 1.0f / zs;
    float u0 = fx * pcx * inv_z + cx;
    float u1 = fy * pcy * inv_z + cy;

    float s0 = expf(sraw[3*i]), s1 = expf(sraw[3*i+1]), s2 = expf(sraw[3*i+2]);
    float qw=qraw[4*i], qx=qraw[4*i+1], qy=qraw[4*i+2], qz=qraw[4*i+3];
    float qn = rsqrtf(qw*qw + qx*qx + qy*qy + qz*qz);
    qw*=qn; qx*=qn; qy*=qn; qz*=qn;
    float r00 = 1.f-2.f*(qy*qy+qz*qz), r01 = 2.f*(qx*qy-qw*qz), r02 = 2.f*(qx*qz+qw*qy);
    float r10 = 2.f*(qx*qy+qw*qz), r11 = 1.f-2.f*(qx*qx+qz*qz), r12 = 2.f*(qy*qz-qw*qx);
    float r20 = 2.f*(qx*qz-qw*qy), r21 = 2.f*(qy*qz+qw*qx), r22 = 1.f-2.f*(qx*qx+qy*qy);

    float v0=s0*s0, v1=s1*s1, v2=s2*s2;
    float c00 = v0*r00*r00 + v1*r01*r01 + v2*r02*r02;
    float c01 = v0*r00*r10 + v1*r01*r11 + v2*r02*r12;
    float c02 = v0*r00*r20 + v1*r01*r21 + v2*r02*r22;
    float c11 = v0*r10*r10 + v1*r11*r11 + v2*r12*r12;
    float c12 = v0*r10*r20 + v1*r11*r21 + v2*r12*r22;
    float c22 = v0*r20*r20 + v1*r21*r21 + v2*r22*r22;

    float limx = 1.3f * (96.0f / (2.0f*fx));
    float limy = 1.3f * (96.0f / (2.0f*fy));
    float txc = fminf(fmaxf(pcx*inv_z, -limx), limx) * zs;
    float tyc = fminf(fmaxf(pcy*inv_z, -limy), limy) * zs;
    float J00 = fx*inv_z, J02 = -fx*txc*inv_z*inv_z;
    float J11 = fy*inv_z, J12 = -fy*tyc*inv_z*inv_z;

    float T00 = J00*R00 + J02*R20, T01 = J00*R01 + J02*R21, T02 = J00*R02 + J02*R22;
    float T10 = J11*R10 + J12*R20, T11 = J11*R11 + J12*R21, T12 = J11*R12 + J12*R22;

    float m00 = T00*c00 + T01*c01 + T02*c02;
    float m01 = T00*c01 + T01*c11 + T02*c12;
    float m02 = T00*c02 + T01*c12 + T02*c22;
    float m10 = T10*c00 + T11*c01 + T12*c02;
    float m11 = T10*c01 + T11*c11 + T12*c12;
    float m12 = T10*c02 + T11*c12 + T12*c22;

    float A  = m00*T00 + m01*T01 + m02*T02 + 0.3f;
    float Bb = m00*T10 + m01*T11 + m02*T12;
    float Cc = m10*T10 + m11*T11 + m12*T12 + 0.3f;

    float det  = A*Cc - Bb*Bb;
    float idet = 1.0f / det;
    float hA = -0.5f * Cc * idet;
    float hC = -0.5f * A  * idet;
    float hB =  Bb * idet;

    float mid = 0.5f * (A + Cc);
    float lam = mid + sqrtf(fmaxf(mid*mid - det, 0.1f));
    float radius = ceilf(3.0f * sqrtf(lam));
    out_areas[2*i]   = radius;
    out_areas[2*i+1] = radius;

    float alpha = 1.0f / (1.0f + __expf(-araw[i]));
    if (!(depth > 0.2f)) alpha = 0.0f;

    float rc2;
    if (alpha * 255.0f <= 1.0f) {
        rc2 = -1.0f;
    } else {
        float theta = 2.0f * __logf(255.0f * alpha);
        rc2 = lam * theta * 1.002f + 1e-2f;
    }

    // SH color
    float wx = R00*t0 + R10*t1 + R20*t2;
    float wy = R01*t0 + R11*t1 + R21*t2;
    float wz = R02*t0 + R12*t1 + R22*t2;
    float dx0 = pwx + wx, dy0 = pwy + wy, dz0 = pwz + wz;
    float dn = rsqrtf(dx0*dx0 + dy0*dy0 + dz0*dz0);
    float x = dx0*dn, y = dy0*dn, z = dz0*dn;
    float xx=x*x, yy=y*y, zz=z*z, xy=x*y, yz=y*z, xz=x*z;

    float b1 = -0.4886025119029199f*y, b2 = 0.4886025119029199f*z, b3 = -0.4886025119029199f*x;
    float b4 =  1.0925484305920792f  * xy;
    float b5 = -1.0925484305920792f  * yz;
    float b6 =  0.31539156525252005f * (2.f*zz - xx - yy);
    float b7 = -1.0925484305920792f  * xz;
    float b8 =  0.5462742152960396f  * (xx - yy);
    float b9  = -0.5900435899266435f * y * (3.f*xx - yy);
    float b10 =  2.890611442640554f  * xy * z;
    float b11 = -0.4570457994644658f * y * (4.f*zz - xx - yy);
    float b12 =  0.3731763325901154f * z * (2.f*zz - 3.f*xx - 3.f*yy);
    float b13 = -0.4570457994644658f * x * (4.f*zz - xx - yy);
    float b14 =  1.445305721320277f  * z * (xx - yy);
    float b15 = -0.5900435899266435f * x * (xx - 3.f*yy);

    const float* hs = highs + 45*i;
    float col[3];
    #pragma unroll
    for (int ch = 0; ch < 3; ch++) {
        float c = 0.28209479177387814f * lows[3*i + ch];
        c += b1  * hs[0*3+ch]  + b2  * hs[1*3+ch]  + b3  * hs[2*3+ch];
        c += b4  * hs[3*3+ch]  + b5  * hs[4*3+ch]  + b6  * hs[5*3+ch];
        c += b7  * hs[6*3+ch]  + b8  * hs[7*3+ch];
        c += b9  * hs[8*3+ch]  + b10 * hs[9*3+ch]  + b11 * hs[10*3+ch];
        c += b12 * hs[11*3+ch] + b13 * hs[12*3+ch] + b14 * hs[13*3+ch];
        c += b15 * hs[14*3+ch];
        col[ch] = fmaxf(c + 0.5f, 0.0f);
    }

    g_p0[i] = make_float4(u0, u1, rc2, hA);
    g_p1[i] = make_float4(hB, hC, alpha, col[0]);
    g_p2[i] = make_float2(col[1], col[2]);

    unsigned int b = __float_as_uint(depth);
    b = (b & 0x80000000u) ? ~b : (b | 0x80000000u);
    g_key[i] = ((unsigned long long)b << 32) | (unsigned int)i;
}

// ---------------- Kernel B: rank-by-counting (exact stable argsort + gather) ----------------
// 128 blocks x 512 threads; 32 gaussians/block, 16-way split of the compare loop.
__global__ void rank_kernel(int n)
{
    __shared__ unsigned long long sk[NMAX];
    int tid = threadIdx.x;
    for (int k = tid; k < n; k += 512) sk[k] = g_key[k];
    __syncthreads();

    int il = tid >> 4;          // 0..31 local gaussian
    int sp = tid & 15;          // split 0..15
    int i  = blockIdx.x * 32 + il;
    if (i >= n) return;
    unsigned long long ki = sk[i];

    int r = 0;
    #pragma unroll 8
    for (int j = sp; j < n; j += 16) r += (sk[j] < ki) ? 1 : 0;

    r += __shfl_down_sync(0xffffffffu, r, 8, 16);
    r += __shfl_down_sync(0xffffffffu, r, 4, 16);
    r += __shfl_down_sync(0xffffffffu, r, 2, 16);
    r += __shfl_down_sync(0xffffffffu, r, 1, 16);

    if (sp == 0) {
        o_p0[r] = g_p0[i];
        o_p1[r] = g_p1[i];
        o_p2[r] = g_p2[i];
    }
}

// ---------------- Kernel C: fused cull + segmented-parallel blend ----------------
// 144 tiles x 512 threads; 16 warps = 16 depth segments, 2 px/thread.
__global__ void __launch_bounds__(512, 1)
blend_kernel(float* __restrict__ out, int n)
{
    __shared__ unsigned swords[NWORDS];
    __shared__ int wsum[4];
    __shared__ unsigned short slist[NMAX];
    __shared__ float4 st0[NSEG][32];
    __shared__ float4 st1[NSEG][32];
    __shared__ float2 st2[NSEG][32];
    __shared__ float4 part[NSEG][64];

    int tile = blockIdx.x;
    int tid = threadIdx.x, lane = tid & 31, warp = tid >> 5;
    float x0 = (float)((tile % 12) * 8), x1 = x0 + 7.0f;
    float y0 = (float)((tile / 12) * 8), y1 = y0 + 7.0f;

    // ---- phase A: cull -> bitmasks (batched loads for MLP) ----
    int nwords = (n + 31) >> 5;
    {
        float4 pv[8];
        #pragma unroll
        for (int k = 0; k < 8; k++) {
            int gi = k * 512 + tid;
            pv[k] = (gi < n) ? o_p0[gi] : make_float4(0.f, 0.f, -1.f, 0.f);
        }
        #pragma unroll
        for (int k = 0; k < 8; k++) {
            int gi = k * 512 + tid;
            float ddx = fmaxf(fmaxf(x0 - pv[k].x, pv[k].x - x1), 0.0f);
            float ddy = fmaxf(fmaxf(y0 - pv[k].y, pv[k].y - y1), 0.0f);
            bool keep = (gi < n) && ((ddx*ddx + ddy*ddy) <= pv[k].z);
            unsigned m = __ballot_sync(0xffffffffu, keep);
            if (lane == 0) swords[k * 16 + warp] = m;
        }
    }
    __syncthreads();

    // ---- phase B: scan + expand ordered survivor list ----
    int c = 0, v = 0;
    if (tid < 128) {
        c = (tid < nwords) ? __popc(swords[tid]) : 0;
        v = c;
        #pragma unroll
        for (int o = 1; o < 32; o <<= 1) {
            int u = __shfl_up_sync(0xffffffffu, v, o);
            if (lane >= o) v += u;
        }
        if (lane == 31) wsum[warp] = v;
    }
    __syncthreads();
    int cnt = wsum[0] + wsum[1] + wsum[2] + wsum[3];
    if (tid < nwords && c) {
        int add = 0;
        #pragma unroll
        for (int w = 0; w < 4; w++) if (w < warp) add += wsum[w];
        int slot = v - c + add;
        unsigned m = swords[tid];
        int base = tid * 32;
        while (m) {
            int b = __ffs(m) - 1; m &= m - 1;
            slist[slot++] = (unsigned short)(base + b);
        }
    }
    __syncthreads();

    // ---- phase C: per-warp segment composite ----
    int Lw = (cnt + NSEG - 1) / NSEG;
    int seg0 = warp * Lw;
    int seg1 = min(seg0 + Lw, cnt);

    int px = lane & 7, py = lane >> 3;
    float fpx  = x0 + (float)px;
    float fpy0 = y0 + (float)py;
    float fpy1 = fpy0 + 4.0f;

    float tau0 = 1.f, tau1 = 1.f;
    float A00=0.f, A01=0.f, A02=0.f, A10=0.f, A11=0.f, A12=0.f;

    for (int cs = seg0; cs < seg1; cs += 32) {
        int t = cs + lane;
        if (t < seg1) {
            int gi = slist[t];
            st0[warp][lane] = o_p0[gi];
            st1[warp][lane] = o_p1[gi];
            st2[warp][lane] = o_p2[gi];
        }
        __syncwarp();
        int m = min(32, seg1 - cs);
        for (int s = 0; s < m; s++) {
            float4 q0 = st0[warp][s];
            float4 q1 = st1[warp][s];
            float2 q2 = st2[warp][s];
            float ddx  = q0.x - fpx;
            float bx   = q1.x * ddx;
            float base = q0.w * ddx * ddx;
            float ddy0 = q0.y - fpy0;
            float ddy1 = q0.y - fpy1;
            float p0 = base + q1.y*ddy0*ddy0 + bx*ddy0;
            float p1 = base + q1.y*ddy1*ddy1 + bx*ddy1;
            float ap0 = fminf(q1.z * __expf(fminf(p0, 0.f)), 0.99f);
            float ap1 = fminf(q1.z * __expf(fminf(p1, 0.f)), 0.99f);
            if (ap0 < (1.0f/255.0f)) ap0 = 0.f;
            if (ap1 < (1.0f/255.0f)) ap1 = 0.f;
            float w0 = ap0 * tau0, w1 = ap1 * tau1;
            A00 += q1.w * w0; A01 += q2.x * w0; A02 += q2.y * w0;
            A10 += q1.w * w1; A11 += q2.x * w1; A12 += q2.y * w1;
            tau0 -= tau0 * ap0;
            tau1 -= tau1 * ap1;
        }
        __syncwarp();
    }
    part[warp][lane]      = make_float4(A00, A01, A02, tau0);
    part[warp][lane + 32] = make_float4(A10, A11, A12, tau1);
    __syncthreads();

    // ---- phase D: fold partials per pixel ----
    if (tid < 64) {
        float T = 1.f, a0 = 0.f, a1 = 0.f, a2 = 0.f;
        #pragma unroll
        for (int w = 0; w < NSEG; w++) {
            float4 q = part[w][tid];
            if (T > 1e-4f) {
                a0 += T * q.x; a1 += T * q.y; a2 += T * q.z;
                T *= q.w;
            }
        }
        int ppx = tid & 7, ppy = tid >> 3;
        int pix = ((tile / 12) * 8 + ppy) * 96 + (tile % 12) * 8 + ppx;
        out[pix]          = a0;
        out[NPIX + pix]   = a1;
        out[2*NPIX + pix] = a2;
    }
}

extern "C" void kernel_launch(void* const* d_in, const int* in_sizes, int n_in,
                              void* d_out, int out_size)
{
    const float* pws   = (const float*)d_in[0];
    const float* lows  = (const float*)d_in[1];
    const float* highs = (const float*)d_in[2];
    const float* araw  = (const float*)d_in[3];
    const float* sraw  = (const float*)d_in[4];
    const float* qraw  = (const float*)d_in[5];
    const float* Rcw   = (const float*)d_in[7];
    const float* tcw   = (const float*)d_in[8];
    const float* cam   = (const float*)d_in[9];
    float* out = (float*)d_out;

    int n = in_sizes[0] / 3;
    if (n > NMAX) n = NMAX;

    float* out_areas = out + 3 * NPIX;

    prep_kernel<<<(n + 31) / 32, 32>>>(pws, lows, highs, araw, sraw, qraw,
                                       Rcw, tcw, cam, out_areas, n);
    rank_kernel<<<(n + 31) / 32, 512>>>(n);
    blend_kernel<<<NTILE, 512>>>(out, n);
}

// round 11
// speedup vs baseline: 4.4224x; 1.0668x over previous
#include <cuda_runtime.h>
#include <math.h>

#define NMAX 4096
#define NPIX (96*96)
#define NTILE 144
#define NWORDS (NMAX/32)
#define NSEG 16
#define PB 32

// ---- packed scratch (device globals) ----
__device__ float4 g_p0[NMAX];   // u0, u1, rc2, hA
__device__ float4 g_p1[NMAX];   // hB, hC, alpha, cr
__device__ float2 g_p2[NMAX];   // cg, cb
__device__ unsigned long long g_key[NMAX];
// depth-sorted
__device__ float4 o_p0[NMAX];
__device__ float4 o_p1[NMAX];
__device__ float2 o_p2[NMAX];

// ---------------- Kernel A: per-gaussian preprocess (coalesced smem staging) ----------------
__global__ void __launch_bounds__(PB, 1)
prep_kernel(const float* __restrict__ pws,
            const float* __restrict__ lows,
            const float* __restrict__ highs,
            const float* __restrict__ araw,
            const float* __restrict__ sraw,
            const float* __restrict__ qraw,
            const float* __restrict__ Rcw,
            const float* __restrict__ tcw,
            const float* __restrict__ cam,
            float* __restrict__ out_areas,
            int n)
{
    __shared__ float s_high[PB*45];
    __shared__ float s_pw[PB*3], s_low[PB*3], s_sr[PB*3], s_q[PB*4], s_a[PB];

    int base = blockIdx.x * PB;
    int tid  = threadIdx.x;

    if (base + PB <= n) {
        // full block: vectorized coalesced staging (all row starts 16B-aligned)
        const float4* H4 = (const float4*)(highs + base*45);
        float4* SH4 = (float4*)s_high;
        #pragma unroll
        for (int k = tid; k < PB*45/4; k += PB) SH4[k] = H4[k];
        const float4* P4 = (const float4*)(pws + base*3);
        const float4* L4 = (const float4*)(lows + base*3);
        const float4* S4 = (const float4*)(sraw + base*3);
        #pragma unroll
        for (int k = tid; k < PB*3/4; k += PB) {
            ((float4*)s_pw)[k]  = P4[k];
            ((float4*)s_low)[k] = L4[k];
            ((float4*)s_sr)[k]  = S4[k];
        }
        const float4* Q4 = (const float4*)(qraw + base*4);
        #pragma unroll
        for (int k = tid; k < PB; k += PB) ((float4*)s_q)[k] = Q4[k];
        if (tid < PB/4) ((float4*)s_a)[tid] = ((const float4*)(araw + base))[tid];
    } else {
        for (int k = tid; k < PB*45 && base*45 + k < n*45; k += PB) s_high[k] = highs[base*45+k];
        for (int k = tid; k < PB*3 && base*3 + k < n*3; k += PB) {
            s_pw[k] = pws[base*3+k]; s_low[k] = lows[base*3+k]; s_sr[k] = sraw[base*3+k];
        }
        for (int k = tid; k < PB*4 && base*4 + k < n*4; k += PB) s_q[k] = qraw[base*4+k];
        if (base + tid < n) s_a[tid] = araw[base + tid];
    }
    __syncthreads();

    int i = base + tid;
    if (i >= n) return;

    float fx = cam[0], fy = cam[1], cx = cam[2], cy = cam[3];
    float R00=Rcw[0],R01=Rcw[1],R02=Rcw[2];
    float R10=Rcw[3],R11=Rcw[4],R12=Rcw[5];
    float R20=Rcw[6],R21=Rcw[7],R22=Rcw[8];
    float t0=tcw[0],t1=tcw[1],t2=tcw[2];

    float pwx=s_pw[3*tid], pwy=s_pw[3*tid+1], pwz=s_pw[3*tid+2];
    float pcx = R00*pwx + R01*pwy + R02*pwz + t0;
    float pcy = R10*pwx + R11*pwy + R12*pwz + t1;
    float pcz = R20*pwx + R21*pwy + R22*pwz + t2;
    float depth = pcz;
    float zs = (depth > 1e-6f) ? depth : 1e-6f;
    float inv_z = 1.0f / zs;
    float u0 = fx * pcx * inv_z + cx;
    float u1 = fy * pcy * inv_z + cy;

    float s0 = __expf(s_sr[3*tid]), s1 = __expf(s_sr[3*tid+1]), s2 = __expf(s_sr[3*tid+2]);
    float qw=s_q[4*tid], qx=s_q[4*tid+1], qy=s_q[4*tid+2], qz=s_q[4*tid+3];
    float qn = rsqrtf(qw*qw + qx*qx + qy*qy + qz*qz);
    qw*=qn; qx*=qn; qy*=qn; qz*=qn;
    float r00 = 1.f-2.f*(qy*qy+qz*qz), r01 = 2.f*(qx*qy-qw*qz), r02 = 2.f*(qx*qz+qw*qy);
    float r10 = 2.f*(qx*qy+qw*qz), r11 = 1.f-2.f*(qx*qx+qz*qz), r12 = 2.f*(qy*qz-qw*qx);
    float r20 = 2.f*(qx*qz-qw*qy), r21 = 2.f*(qy*qz+qw*qx), r22 = 1.f-2.f*(qx*qx+qy*qy);

    float v0=s0*s0, v1=s1*s1, v2=s2*s2;
    float c00 = v0*r00*r00 + v1*r01*r01 + v2*r02*r02;
    float c01 = v0*r00*r10 + v1*r01*r11 + v2*r02*r12;
    float c02 = v0*r00*r20 + v1*r01*r21 + v2*r02*r22;
    float c11 = v0*r10*r10 + v1*r11*r11 + v2*r12*r12;
    float c12 = v0*r10*r20 + v1*r11*r21 + v2*r12*r22;
    float c22 = v0*r20*r20 + v1*r21*r21 + v2*r22*r22;

    float limx = 1.3f * (96.0f / (2.0f*fx));
    float limy = 1.3f * (96.0f / (2.0f*fy));
    float txc = fminf(fmaxf(pcx*inv_z, -limx), limx) * zs;
    float tyc = fminf(fmaxf(pcy*inv_z, -limy), limy) * zs;
    float J00 = fx*inv_z, J02 = -fx*txc*inv_z*inv_z;
    float J11 = fy*inv_z, J12 = -fy*tyc*inv_z*inv_z;

    float T00 = J00*R00 + J02*R20, T01 = J00*R01 + J02*R21, T02 = J00*R02 + J02*R22;
    float T10 = J11*R10 + J12*R20, T11 = J11*R11 + J12*R21, T12 = J11*R12 + J12*R22;

    float m00 = T00*c00 + T01*c01 + T02*c02;
    float m01 = T00*c01 + T01*c11 + T02*c12;
    float m02 = T00*c02 + T01*c12 + T02*c22;
    float m10 = T10*c00 + T11*c01 + T12*c02;
    float m11 = T10*c01 + T11*c11 + T12*c12;
    float m12 = T10*c02 + T11*c12 + T12*c22;

    float A  = m00*T00 + m01*T01 + m02*T02 + 0.3f;
    float Bb = m00*T10 + m01*T11 + m02*T12;
    float Cc = m10*T10 + m11*T11 + m12*T12 + 0.3f;

    float det  = A*Cc - Bb*Bb;
    float idet = 1.0f / det;
    float hA = -0.5f * Cc * idet;
    float hC = -0.5f * A  * idet;
    float hB =  Bb * idet;

    float mid = 0.5f * (A + Cc);
    float lam = mid + sqrtf(fmaxf(mid*mid - det, 0.1f));
    float radius = ceilf(3.0f * sqrtf(lam));
    out_areas[2*i]   = radius;
    out_areas[2*i+1] = radius;

    float alpha = 1.0f / (1.0f + __expf(-s_a[tid]));
    if (!(depth > 0.2f)) alpha = 0.0f;

    float rc2;
    if (alpha * 255.0f <= 1.0f) {
        rc2 = -1.0f;
    } else {
        float theta = 2.0f * __logf(255.0f * alpha);
        rc2 = lam * theta * 1.002f + 1e-2f;
    }

    // SH color
    float wx = R00*t0 + R10*t1 + R20*t2;
    float wy = R01*t0 + R11*t1 + R21*t2;
    float wz = R02*t0 + R12*t1 + R22*t2;
    float dx0 = pwx + wx, dy0 = pwy + wy, dz0 = pwz + wz;
    float dn = rsqrtf(dx0*dx0 + dy0*dy0 + dz0*dz0);
    float x = dx0*dn, y = dy0*dn, z = dz0*dn;
    float xx=x*x, yy=y*y, zz=z*z, xy=x*y, yz=y*z, xz=x*z;

    float b1 = -0.4886025119029199f*y, b2 = 0.4886025119029199f*z, b3 = -0.4886025119029199f*x;
    float b4 =  1.0925484305920792f  * xy;
    float b5 = -1.0925484305920792f  * yz;
    float b6 =  0.31539156525252005f * (2.f*zz - xx - yy);
    float b7 = -1.0925484305920792f  * xz;
    float b8 =  0.5462742152960396f  * (xx - yy);
    float b9  = -0.5900435899266435f * y * (3.f*xx - yy);
    float b10 =  2.890611442640554f  * xy * z;
    float b11 = -0.4570457994644658f * y * (4.f*zz - xx - yy);
    float b12 =  0.3731763325901154f * z * (2.f*zz - 3.f*xx - 3.f*yy);
    float b13 = -0.4570457994644658f * x * (4.f*zz - xx - yy);
    float b14 =  1.445305721320277f  * z * (xx - yy);
    float b15 = -0.5900435899266435f * x * (xx - 3.f*yy);

    const float* hs = s_high + 45*tid;
    float col[3];
    #pragma unroll
    for (int ch = 0; ch < 3; ch++) {
        float c = 0.28209479177387814f * s_low[3*tid + ch];
        c += b1  * hs[0*3+ch]  + b2  * hs[1*3+ch]  + b3  * hs[2*3+ch];
        c += b4  * hs[3*3+ch]  + b5  * hs[4*3+ch]  + b6  * hs[5*3+ch];
        c += b7  * hs[6*3+ch]  + b8  * hs[7*3+ch];
        c += b9  * hs[8*3+ch]  + b10 * hs[9*3+ch]  + b11 * hs[10*3+ch];
        c += b12 * hs[11*3+ch] + b13 * hs[12*3+ch] + b14 * hs[13*3+ch];
        c += b15 * hs[14*3+ch];
        col[ch] = fmaxf(c + 0.5f, 0.0f);
    }

    g_p0[i] = make_float4(u0, u1, rc2, hA);
    g_p1[i] = make_float4(hB, hC, alpha, col[0]);
    g_p2[i] = make_float2(col[1], col[2]);

    unsigned int b = __float_as_uint(depth);
    b = (b & 0x80000000u) ? ~b : (b | 0x80000000u);
    g_key[i] = ((unsigned long long)b << 32) | (unsigned int)i;
}

// ---------------- Kernel B: rank-by-counting (exact stable argsort + gather) ----------------
__global__ void rank_kernel(int n)
{
    __shared__ unsigned long long sk[NMAX];
    int tid = threadIdx.x;
    for (int k = tid; k < n; k += 512) sk[k] = g_key[k];
    __syncthreads();

    int il = tid >> 4;
    int sp = tid & 15;
    int i  = blockIdx.x * 32 + il;
    if (i >= n) return;
    unsigned long long ki = sk[i];

    int r = 0;
    #pragma unroll 8
    for (int j = sp; j < n; j += 16) r += (sk[j] < ki) ? 1 : 0;

    r += __shfl_down_sync(0xffffffffu, r, 8, 16);
    r += __shfl_down_sync(0xffffffffu, r, 4, 16);
    r += __shfl_down_sync(0xffffffffu, r, 2, 16);
    r += __shfl_down_sync(0xffffffffu, r, 1, 16);

    if (sp == 0) {
        o_p0[r] = g_p0[i];
        o_p1[r] = g_p1[i];
        o_p2[r] = g_p2[i];
    }
}

// ---------------- Kernel C: fused cull + segmented-parallel blend ----------------
__global__ void __launch_bounds__(512, 1)
blend_kernel(float* __restrict__ out, int n)
{
    __shared__ unsigned swords[NWORDS];
    __shared__ int wsum[4];
    __shared__ unsigned short slist[NMAX];
    __shared__ float4 st0[NSEG][32];
    __shared__ float4 st1[NSEG][32];
    __shared__ float2 st2[NSEG][32];
    __shared__ float4 part[NSEG][64];

    int tile = blockIdx.x;
    int tid = threadIdx.x, lane = tid & 31, warp = tid >> 5;
    float x0 = (float)((tile % 12) * 8), x1 = x0 + 7.0f;
    float y0 = (float)((tile / 12) * 8), y1 = y0 + 7.0f;

    // ---- phase A: cull -> bitmasks (batched loads for MLP) ----
    int nwords = (n + 31) >> 5;
    {
        float4 pv[8];
        #pragma unroll
        for (int k = 0; k < 8; k++) {
            int gi = k * 512 + tid;
            pv[k] = (gi < n) ? o_p0[gi] : make_float4(0.f, 0.f, -1.f, 0.f);
        }
        #pragma unroll
        for (int k = 0; k < 8; k++) {
            int gi = k * 512 + tid;
            float ddx = fmaxf(fmaxf(x0 - pv[k].x, pv[k].x - x1), 0.0f);
            float ddy = fmaxf(fmaxf(y0 - pv[k].y, pv[k].y - y1), 0.0f);
            bool keep = (gi < n) && ((ddx*ddx + ddy*ddy) <= pv[k].z);
            unsigned m = __ballot_sync(0xffffffffu, keep);
            if (lane == 0) swords[k * 16 + warp] = m;
        }
    }
    __syncthreads();

    // ---- phase B: scan + expand ordered survivor list ----
    int c = 0, v = 0;
    if (tid < 128) {
        c = (tid < nwords) ? __popc(swords[tid]) : 0;
        v = c;
        #pragma unroll
        for (int o = 1; o < 32; o <<= 1) {
            int u = __shfl_up_sync(0xffffffffu, v, o);
            if (lane >= o) v += u;
        }
        if (lane == 31) wsum[warp] = v;
    }
    __syncthreads();
    int cnt = wsum[0] + wsum[1] + wsum[2] + wsum[3];
    if (tid < nwords && c) {
        int add = 0;
        #pragma unroll
        for (int w = 0; w < 4; w++) if (w < warp) add += wsum[w];
        int slot = v - c + add;
        unsigned m = swords[tid];
        int base = tid * 32;
        while (m) {
            int b = __ffs(m) - 1; m &= m - 1;
            slist[slot++] = (unsigned short)(base + b);
        }
    }
    __syncthreads();

    // ---- phase C: per-warp segment composite ----
    int Lw = (cnt + NSEG - 1) / NSEG;
    int seg0 = warp * Lw;
    int seg1 = min(seg0 + Lw, cnt);

    int px = lane & 7, py = lane >> 3;
    float fpx  = x0 + (float)px;
    float fpy0 = y0 + (float)py;
    float fpy1 = fpy0 + 4.0f;

    float tau0 = 1.f, tau1 = 1.f;
    float A00=0.f, A01=0.f, A02=0.f, A10=0.f, A11=0.f, A12=0.f;

    for (int cs = seg0; cs < seg1; cs += 32) {
        int t = cs + lane;
        if (t < seg1) {
            int gi = slist[t];
            st0[warp][lane] = o_p0[gi];
            st1[warp][lane] = o_p1[gi];
            st2[warp][lane] = o_p2[gi];
        }
        __syncwarp();
        int m = min(32, seg1 - cs);
        for (int s = 0; s < m; s++) {
            float4 q0 = st0[warp][s];
            float4 q1 = st1[warp][s];
            float2 q2 = st2[warp][s];
            float ddx  = q0.x - fpx;
            float bx   = q1.x * ddx;
            float base = q0.w * ddx * ddx;
            float ddy0 = q0.y - fpy0;
            float ddy1 = q0.y - fpy1;
            float p0 = base + q1.y*ddy0*ddy0 + bx*ddy0;
            float p1 = base + q1.y*ddy1*ddy1 + bx*ddy1;
            float ap0 = fminf(q1.z * __expf(fminf(p0, 0.f)), 0.99f);
            float ap1 = fminf(q1.z * __expf(fminf(p1, 0.f)), 0.99f);
            if (ap0 < (1.0f/255.0f)) ap0 = 0.f;
            if (ap1 < (1.0f/255.0f)) ap1 = 0.f;
            float w0 = ap0 * tau0, w1 = ap1 * tau1;
            A00 += q1.w * w0; A01 += q2.x * w0; A02 += q2.y * w0;
            A10 += q1.w * w1; A11 += q2.x * w1; A12 += q2.y * w1;
            tau0 -= tau0 * ap0;
            tau1 -= tau1 * ap1;
        }
        __syncwarp();
    }
    part[warp][lane]      = make_float4(A00, A01, A02, tau0);
    part[warp][lane + 32] = make_float4(A10, A11, A12, tau1);
    __syncthreads();

    // ---- phase D: fold partials per pixel ----
    if (tid < 64) {
        float T = 1.f, a0 = 0.f, a1 = 0.f, a2 = 0.f;
        #pragma unroll
        for (int w = 0; w < NSEG; w++) {
            float4 q = part[w][tid];
            if (T > 1e-4f) {
                a0 += T * q.x; a1 += T * q.y; a2 += T * q.z;
                T *= q.w;
            }
        }
        int ppx = tid & 7, ppy = tid >> 3;
        int pix = ((tile / 12) * 8 + ppy) * 96 + (tile % 12) * 8 + ppx;
        out[pix]          = a0;
        out[NPIX + pix]   = a1;
        out[2*NPIX + pix] = a2;
    }
}

extern "C" void kernel_launch(void* const* d_in, const int* in_sizes, int n_in,
                              void* d_out, int out_size)
{
    const float* pws   = (const float*)d_in[0];
    const float* lows  = (const float*)d_in[1];
    const float* highs = (const float*)d_in[2];
    const float* araw  = (const float*)d_in[3];
    const float* sraw  = (const float*)d_in[4];
    const float* qraw  = (const float*)d_in[5];
    const float* Rcw   = (const float*)d_in[7];
    const float* tcw   = (const float*)d_in[8];
    const float* cam   = (const float*)d_in[9];
    float* out = (float*)d_out;

    int n = in_sizes[0] / 3;
    if (n > NMAX) n = NMAX;

    float* out_areas = out + 3 * NPIX;

    prep_kernel<<<(n + PB - 1) / PB, PB>>>(pws, lows, highs, araw, sraw, qraw,
                                           Rcw, tcw, cam, out_areas, n);
    rank_kernel<<<(n + 31) / 32, 512>>>(n);
    blend_kernel<<<NTILE, 512>>>(out, n);
}